// round 15
// baseline (speedup 1.0000x reference)
#include <cuda_runtime.h>
#include <cuda_bf16.h>
#include <cstdint>

#define HW      65536
#define TPB     128
#define TILE_PX 128
#define NBLK    8192
#define PITCHX  36

typedef unsigned long long u64;
typedef uint32_t u32;

__device__ __forceinline__ u64 ffma2(u64 a, u64 b, u64 c) {
    u64 d;
    asm("fma.rn.f32x2 %0, %1, %2, %3;" : "=l"(d) : "l"(a), "l"(b), "l"(c));
    return d;
}
__device__ __forceinline__ u64 packf2(float lo, float hi) {
    u64 d;
    asm("mov.b64 %0, {%1, %2};" : "=l"(d) : "f"(lo), "f"(hi));
    return d;
}
__device__ __forceinline__ void unpackf2(u64 v, float& lo, float& hi) {
    asm("mov.b64 {%0, %1}, %2;" : "=f"(lo), "=f"(hi) : "l"(v));
}
__device__ __forceinline__ void bsplit(float a, uint16_t& h, uint16_t& l) {
    __nv_bfloat16 hb = __float2bfloat16_rn(a);
    h = __bfloat16_as_ushort(hb);
    float r = a - __bfloat162float(hb);
    l = __bfloat16_as_ushort(__float2bfloat16_rn(r));
}
__device__ __forceinline__ void mma16816(float* c, const u32* a, u32 b0, u32 b1) {
    asm volatile(
        "mma.sync.aligned.m16n8k16.row.col.f32.bf16.bf16.f32 "
        "{%0,%1,%2,%3}, {%4,%5,%6,%7}, {%8,%9}, {%0,%1,%2,%3};"
        : "+f"(c[0]), "+f"(c[1]), "+f"(c[2]), "+f"(c[3])
        : "r"(a[0]), "r"(a[1]), "r"(a[2]), "r"(a[3]), "r"(b0), "r"(b1));
}

__global__ void __launch_bounds__(TPB, 3)
fused_mma2_kernel(
    const float* __restrict__ kv_in, const float* __restrict__ q_in,
    const float* __restrict__ key_w, const float* __restrict__ key_b,
    const float* __restrict__ value_w, const float* __restrict__ value_b,
    const float* __restrict__ query_w, const float* __restrict__ query_b,
    const float* __restrict__ scale_p,
    const float* __restrict__ d1_w, const float* __restrict__ d2_w,
    const float* __restrict__ d3_w, const float* __restrict__ d3_b,
    float* __restrict__ out)
{
    // interleaved B fragment table: [s][j][lane] = {hi_pair64, lo_pair64}
    __shared__ ulonglong2 sBP[4 * 12 * 32];   // 24 KB
    __shared__ u64 sBiasP[48];
    __shared__ u64 sD1p[32 * 8];
    __shared__ u64 sD2p[16 * 4];
    __shared__ u64 sD3p[8 * 8];
    __shared__ float sB3[16];
    __shared__ float sScl;
    __shared__ __align__(16) float sX[TILE_PX * PITCHX];   // 18 KB

    const int tid  = threadIdx.x;
    const int lane = tid & 31;
    const int wrp  = tid >> 5;      // 0..3
    const int gid  = lane >> 2;
    const int tig  = lane & 3;

    // ---- stage B fragment table ----
    for (int i = tid; i < 4 * 12 * 32; i += TPB) {
        int l = i & 31, j = (i >> 5) % 12, s = i / (12 * 32);
        int n = j * 8 + (l >> 2);
        int k0 = s * 16 + 2 * (l & 3);
        const float* wrow = (n < 32) ? (key_w + n * 64)
                          : (n < 64) ? (value_w + (n - 32) * 64)
                                     : (query_w + (n - 64) * 64);
        float w00 = wrow[k0],     w01 = wrow[k0 + 1];
        float w10 = wrow[k0 + 8], w11 = wrow[k0 + 9];
        uint16_t h00, l00, h01, l01, h10, l10, h11, l11;
        bsplit(w00, h00, l00); bsplit(w01, h01, l01);
        bsplit(w10, h10, l10); bsplit(w11, h11, l11);
        u32 bh0 = (u32)h00 | ((u32)h01 << 16);
        u32 bh1 = (u32)h10 | ((u32)h11 << 16);
        u32 bl0 = (u32)l00 | ((u32)l01 << 16);
        u32 bl1 = (u32)l10 | ((u32)l11 << 16);
        ulonglong2 v;
        v.x = ((u64)bh1 << 32) | bh0;
        v.y = ((u64)bl1 << 32) | bl0;
        sBP[i] = v;
    }
    if (tid < 48) {
        int o0 = 2 * tid, o1 = o0 + 1;
        float b0 = (o0 < 32) ? key_b[o0] : (o0 < 64) ? value_b[o0 - 32] : query_b[o0 - 64];
        float b1 = (o1 < 32) ? key_b[o1] : (o1 < 64) ? value_b[o1 - 32] : query_b[o1 - 64];
        sBiasP[tid] = packf2(b0, b1);
    }
    for (int i = tid; i < 32 * 8; i += TPB) {
        int c = i >> 3, j = i & 7;
        sD1p[c * 8 + j] = packf2(d1_w[(2 * j) * 32 + c], d1_w[(2 * j + 1) * 32 + c]);
    }
    if (tid < 64) {
        int c = tid >> 2, j = tid & 3;
        sD2p[c * 4 + j] = packf2(d2_w[(2 * j) * 16 + c], d2_w[(2 * j + 1) * 16 + c]);
    }
    if (tid >= 64 && tid < 128) {
        int i = tid - 64;
        int c = i >> 3, j = i & 7;
        sD3p[c * 8 + j] = packf2(d3_w[(2 * j) * 8 + c], d3_w[(2 * j + 1) * 8 + c]);
    }
    if (tid < 16) sB3[tid] = d3_b[tid];
    if (tid == 0) sScl = scale_p[0];
    __syncthreads();

    const int p0   = blockIdx.x * TILE_PX;
    const int b    = p0 >> 16;
    const int poff = p0 & (HW - 1);
    const float* kvb = kv_in + (size_t)b * 64 * HW + poff;
    const float* qb  = q_in  + (size_t)b * 64 * HW + poff;

    // warp covers px rows [32*wrp, 32*wrp+32): 2 m16 tiles (mt = 0,1)
    const int pxr0 = 32 * wrp + gid;

    float acc[2][12][4];
    #pragma unroll
    for (int mt = 0; mt < 2; ++mt)
        #pragma unroll
        for (int j = 0; j < 12; ++j)
            #pragma unroll
            for (int e = 0; e < 4; ++e) acc[mt][j][e] = 0.0f;

    #pragma unroll
    for (int s = 0; s < 4; ++s) {
        u32 ah[2][4], al[2][4];

        // ---- kv A fragments, both row-tiles ----
        #pragma unroll
        for (int mt = 0; mt < 2; ++mt) {
            float av[8];
            #pragma unroll
            for (int cc = 0; cc < 2; ++cc)
                #pragma unroll
                for (int rr = 0; rr < 2; ++rr)
                    #pragma unroll
                    for (int e = 0; e < 2; ++e) {
                        int c  = s * 16 + 2 * tig + e + 8 * cc;
                        int px = pxr0 + 16 * mt + 8 * rr;
                        av[(rr + 2 * cc) * 2 + e] = __ldg(kvb + (size_t)c * HW + px);
                    }
            #pragma unroll
            for (int i = 0; i < 4; ++i) {
                uint16_t h0, l0, h1, l1;
                bsplit(av[2 * i], h0, l0); bsplit(av[2 * i + 1], h1, l1);
                ah[mt][i] = (u32)h0 | ((u32)h1 << 16);
                al[mt][i] = (u32)l0 | ((u32)l1 << 16);
            }
        }
        #pragma unroll
        for (int j = 0; j < 8; ++j) {
            ulonglong2 bp = sBP[s * 384 + j * 32 + lane];
            u32 bh0 = (u32)bp.x, bh1 = (u32)(bp.x >> 32);
            u32 bl0 = (u32)bp.y, bl1 = (u32)(bp.y >> 32);
            #pragma unroll
            for (int mt = 0; mt < 2; ++mt) {
                mma16816(acc[mt][j], ah[mt], bh0, bh1);
                mma16816(acc[mt][j], ah[mt], bl0, bl1);
                mma16816(acc[mt][j], al[mt], bh0, bh1);
            }
        }

        // ---- q A fragments, both row-tiles (reuse regs) ----
        #pragma unroll
        for (int mt = 0; mt < 2; ++mt) {
            float av[8];
            #pragma unroll
            for (int cc = 0; cc < 2; ++cc)
                #pragma unroll
                for (int rr = 0; rr < 2; ++rr)
                    #pragma unroll
                    for (int e = 0; e < 2; ++e) {
                        int c  = s * 16 + 2 * tig + e + 8 * cc;
                        int px = pxr0 + 16 * mt + 8 * rr;
                        av[(rr + 2 * cc) * 2 + e] = __ldg(qb + (size_t)c * HW + px);
                    }
            #pragma unroll
            for (int i = 0; i < 4; ++i) {
                uint16_t h0, l0, h1, l1;
                bsplit(av[2 * i], h0, l0); bsplit(av[2 * i + 1], h1, l1);
                ah[mt][i] = (u32)h0 | ((u32)h1 << 16);
                al[mt][i] = (u32)l0 | ((u32)l1 << 16);
            }
        }
        #pragma unroll
        for (int j = 8; j < 12; ++j) {
            ulonglong2 bp = sBP[s * 384 + j * 32 + lane];
            u32 bh0 = (u32)bp.x, bh1 = (u32)(bp.x >> 32);
            u32 bl0 = (u32)bp.y, bl1 = (u32)(bp.y >> 32);
            #pragma unroll
            for (int mt = 0; mt < 2; ++mt) {
                mma16816(acc[mt][j], ah[mt], bh0, bh1);
                mma16816(acc[mt][j], ah[mt], bl0, bl1);
                mma16816(acc[mt][j], al[mt], bh0, bh1);
            }
        }
    }

    // ---- gate in registers; x -> sX ----
    {
        const float scl = sScl;
        #pragma unroll
        for (int mt = 0; mt < 2; ++mt) {
            #pragma unroll
            for (int j = 0; j < 4; ++j) {
                float bk0, bk1, bv0, bv1, bq0, bq1;
                unpackf2(sBiasP[4 * j + tig],      bk0, bk1);
                unpackf2(sBiasP[16 + 4 * j + tig], bv0, bv1);
                unpackf2(sBiasP[32 + 4 * j + tig], bq0, bq1);
                #pragma unroll
                for (int rr = 0; rr < 2; ++rr) {
                    float kk0 = acc[mt][j][2 * rr]     + bk0;
                    float kk1 = acc[mt][j][2 * rr + 1] + bk1;
                    float vv0 = acc[mt][j + 4][2 * rr]     + bv0;
                    float vv1 = acc[mt][j + 4][2 * rr + 1] + bv1;
                    float qq0 = acc[mt][j + 8][2 * rr]     + bq0;
                    float qq1 = acc[mt][j + 8][2 * rr + 1] + bq1;
                    float z0 = kk0 * qq0 * scl;
                    float z1 = kk1 * qq1 * scl;
                    float x0 = vv0 * __fdividef(1.0f, 1.0f + __expf(-z0));
                    float x1 = vv1 * __fdividef(1.0f, 1.0f + __expf(-z1));
                    int px = pxr0 + 16 * mt + 8 * rr;
                    *reinterpret_cast<float2*>(&sX[px * PITCHX + 8 * j + 2 * tig]) =
                        make_float2(x0, x1);
                }
            }
        }
    }
    __syncthreads();

    // ---- chain: one thread per pixel ----
    {
        const int px = tid;
        const float* row = sX + px * PITCHX;

        float x[32];
        #pragma unroll
        for (int o = 0; o < 32; o += 4) {
            float4 v4 = *reinterpret_cast<const float4*>(row + o);
            x[o] = v4.x; x[o+1] = v4.y; x[o+2] = v4.z; x[o+3] = v4.w;
        }

        u64 h1p[8];
        #pragma unroll
        for (int j = 0; j < 8; ++j) h1p[j] = 0ull;
        #pragma unroll
        for (int c = 0; c < 32; ++c) {
            u64 xx = packf2(x[c], x[c]);
            const ulonglong2* wr = reinterpret_cast<const ulonglong2*>(&sD1p[c * 8]);
            #pragma unroll
            for (int j = 0; j < 4; ++j) {
                ulonglong2 w = wr[j];
                h1p[2*j]   = ffma2(xx, w.x, h1p[2*j]);
                h1p[2*j+1] = ffma2(xx, w.y, h1p[2*j+1]);
            }
        }
        float h1[16];
        #pragma unroll
        for (int j = 0; j < 8; ++j) {
            float lo, hi; unpackf2(h1p[j], lo, hi);
            h1[2*j]   = fmaxf(lo, 0.0f);
            h1[2*j+1] = fmaxf(hi, 0.0f);
        }

        u64 h2p[4];
        #pragma unroll
        for (int j = 0; j < 4; ++j) h2p[j] = 0ull;
        #pragma unroll
        for (int c = 0; c < 16; ++c) {
            u64 xx = packf2(h1[c], h1[c]);
            const ulonglong2* wr = reinterpret_cast<const ulonglong2*>(&sD2p[c * 4]);
            #pragma unroll
            for (int j = 0; j < 2; ++j) {
                ulonglong2 w = wr[j];
                h2p[2*j]   = ffma2(xx, w.x, h2p[2*j]);
                h2p[2*j+1] = ffma2(xx, w.y, h2p[2*j+1]);
            }
        }
        float h2[8];
        #pragma unroll
        for (int j = 0; j < 4; ++j) {
            float lo, hi; unpackf2(h2p[j], lo, hi);
            h2[2*j]   = fmaxf(lo, 0.0f);
            h2[2*j+1] = fmaxf(hi, 0.0f);
        }

        u64 o16p[8];
        {
            const u64* b3p = reinterpret_cast<const u64*>(sB3);
            #pragma unroll
            for (int j = 0; j < 8; ++j) o16p[j] = b3p[j];
        }
        #pragma unroll
        for (int c = 0; c < 8; ++c) {
            u64 xx = packf2(h2[c], h2[c]);
            const ulonglong2* wr = reinterpret_cast<const ulonglong2*>(&sD3p[c * 8]);
            #pragma unroll
            for (int j = 0; j < 4; ++j) {
                ulonglong2 w = wr[j];
                o16p[2*j]   = ffma2(xx, w.x, o16p[2*j]);
                o16p[2*j+1] = ffma2(xx, w.y, o16p[2*j+1]);
            }
        }

        float* op = out + ((size_t)b * 16) * HW + poff + px;
        #pragma unroll
        for (int j = 0; j < 8; ++j) {
            float lo, hi; unpackf2(o16p[j], lo, hi);
            op[(size_t)(2*j) * HW]   = lo;
            op[(size_t)(2*j+1) * HW] = hi;
        }
    }
}

extern "C" void kernel_launch(void* const* d_in, const int* in_sizes, int n_in,
                              void* d_out, int out_size)
{
    fused_mma2_kernel<<<NBLK, TPB>>>(
        (const float*)d_in[0], (const float*)d_in[1],
        (const float*)d_in[2], (const float*)d_in[3],
        (const float*)d_in[4], (const float*)d_in[5],
        (const float*)d_in[6], (const float*)d_in[7],
        (const float*)d_in[8],
        (const float*)d_in[9], (const float*)d_in[10],
        (const float*)d_in[11], (const float*)d_in[12],
        (float*)d_out);
}

// round 17
// speedup vs baseline: 1.1783x; 1.1783x over previous
#include <cuda_runtime.h>
#include <cuda_bf16.h>
#include <cstdint>

#define HW      65536
#define TPB     256
#define TILE_PX 128
#define NBLK    8192
#define PITCHX  36

typedef unsigned long long u64;
typedef uint32_t u32;

__device__ __forceinline__ u64 ffma2(u64 a, u64 b, u64 c) {
    u64 d;
    asm("fma.rn.f32x2 %0, %1, %2, %3;" : "=l"(d) : "l"(a), "l"(b), "l"(c));
    return d;
}
__device__ __forceinline__ u64 packf2(float lo, float hi) {
    u64 d;
    asm("mov.b64 %0, {%1, %2};" : "=l"(d) : "f"(lo), "f"(hi));
    return d;
}
__device__ __forceinline__ void unpackf2(u64 v, float& lo, float& hi) {
    asm("mov.b64 {%0, %1}, %2;" : "=f"(lo), "=f"(hi) : "l"(v));
}
// scalar split (staging only)
__device__ __forceinline__ void bsplit(float a, uint16_t& h, uint16_t& l) {
    __nv_bfloat16 hb = __float2bfloat16_rn(a);
    h = __bfloat16_as_ushort(hb);
    float r = a - __bfloat162float(hb);
    l = __bfloat16_as_ushort(__float2bfloat16_rn(r));
}
// vectorized split of a pair -> packed hi / lo fragments (e0 in low half)
__device__ __forceinline__ void bsplit2(float a0, float a1, u32& hi, u32& lo) {
    u32 h;
    asm("cvt.rn.bf16x2.f32 %0, %1, %2;" : "=r"(h) : "f"(a1), "f"(a0));
    float f0 = __uint_as_float(h << 16);
    float f1 = __uint_as_float(h & 0xffff0000u);
    float r0 = a0 - f0;
    float r1 = a1 - f1;
    u32 l;
    asm("cvt.rn.bf16x2.f32 %0, %1, %2;" : "=r"(l) : "f"(r1), "f"(r0));
    hi = h; lo = l;
}
__device__ __forceinline__ void mma16816(float* c, const u32* a, u32 b0, u32 b1) {
    asm volatile(
        "mma.sync.aligned.m16n8k16.row.col.f32.bf16.bf16.f32 "
        "{%0,%1,%2,%3}, {%4,%5,%6,%7}, {%8,%9}, {%0,%1,%2,%3};"
        : "+f"(c[0]), "+f"(c[1]), "+f"(c[2]), "+f"(c[3])
        : "r"(a[0]), "r"(a[1]), "r"(a[2]), "r"(a[3]), "r"(b0), "r"(b1));
}

__global__ void __launch_bounds__(TPB, 2)
fused_mma3_kernel(
    const float* __restrict__ kv_in, const float* __restrict__ q_in,
    const float* __restrict__ key_w, const float* __restrict__ key_b,
    const float* __restrict__ value_w, const float* __restrict__ value_b,
    const float* __restrict__ query_w, const float* __restrict__ query_b,
    const float* __restrict__ scale_p,
    const float* __restrict__ d1_w, const float* __restrict__ d2_w,
    const float* __restrict__ d3_w, const float* __restrict__ d3_b,
    float* __restrict__ out)
{
    // interleaved B fragment table: [s][j][lane] = {hi_pair64, lo_pair64}
    __shared__ ulonglong2 sBP[4 * 12 * 32];   // 24 KB
    __shared__ u64 sBiasP[48];
    __shared__ u64 sD1p[32 * 8];
    __shared__ u64 sD2p[16 * 4];
    __shared__ u64 sD3p[8 * 8];
    __shared__ float sB3[16];
    __shared__ float sScl;
    __shared__ __align__(16) float sX[TILE_PX * PITCHX];   // 18 KB

    const int tid  = threadIdx.x;
    const int lane = tid & 31;
    const int wrp  = tid >> 5;      // 0..7
    const int gid  = lane >> 2;
    const int tig  = lane & 3;

    // ---- stage B fragment table ----
    for (int i = tid; i < 4 * 12 * 32; i += TPB) {
        int l = i & 31, j = (i >> 5) % 12, s = i / (12 * 32);
        int n = j * 8 + (l >> 2);
        int k0 = s * 16 + 2 * (l & 3);
        const float* wrow = (n < 32) ? (key_w + n * 64)
                          : (n < 64) ? (value_w + (n - 32) * 64)
                                     : (query_w + (n - 64) * 64);
        float w00 = wrow[k0],     w01 = wrow[k0 + 1];
        float w10 = wrow[k0 + 8], w11 = wrow[k0 + 9];
        uint16_t h00, l00, h01, l01, h10, l10, h11, l11;
        bsplit(w00, h00, l00); bsplit(w01, h01, l01);
        bsplit(w10, h10, l10); bsplit(w11, h11, l11);
        u32 bh0 = (u32)h00 | ((u32)h01 << 16);
        u32 bh1 = (u32)h10 | ((u32)h11 << 16);
        u32 bl0 = (u32)l00 | ((u32)l01 << 16);
        u32 bl1 = (u32)l10 | ((u32)l11 << 16);
        ulonglong2 v;
        v.x = ((u64)bh1 << 32) | bh0;
        v.y = ((u64)bl1 << 32) | bl0;
        sBP[i] = v;
    }
    if (tid < 48) {
        int o0 = 2 * tid, o1 = o0 + 1;
        float b0 = (o0 < 32) ? key_b[o0] : (o0 < 64) ? value_b[o0 - 32] : query_b[o0 - 64];
        float b1 = (o1 < 32) ? key_b[o1] : (o1 < 64) ? value_b[o1 - 32] : query_b[o1 - 64];
        sBiasP[tid] = packf2(b0, b1);
    }
    for (int i = tid; i < 32 * 8; i += TPB) {
        int c = i >> 3, j = i & 7;
        sD1p[c * 8 + j] = packf2(d1_w[(2 * j) * 32 + c], d1_w[(2 * j + 1) * 32 + c]);
    }
    if (tid < 64) {
        int c = tid >> 2, j = tid & 3;
        sD2p[c * 4 + j] = packf2(d2_w[(2 * j) * 16 + c], d2_w[(2 * j + 1) * 16 + c]);
    }
    if (tid >= 64 && tid < 128) {
        int i = tid - 64;
        int c = i >> 3, j = i & 7;
        sD3p[c * 8 + j] = packf2(d3_w[(2 * j) * 8 + c], d3_w[(2 * j + 1) * 8 + c]);
    }
    if (tid < 16) sB3[tid] = d3_b[tid];
    if (tid == 0) sScl = scale_p[0];
    __syncthreads();

    const int p0   = blockIdx.x * TILE_PX;
    const int b    = p0 >> 16;
    const int poff = p0 & (HW - 1);
    const float* kvb = kv_in + (size_t)b * 64 * HW + poff;
    const float* qb  = q_in  + (size_t)b * 64 * HW + poff;

    const int pxr = 16 * wrp + gid;

    float acc[12][4];
    #pragma unroll
    for (int j = 0; j < 12; ++j)
        #pragma unroll
        for (int e = 0; e < 4; ++e) acc[j][e] = 0.0f;

    #pragma unroll
    for (int s = 0; s < 4; ++s) {
        // ---- batched loads: all 16 LDG.32 up front (MLP ~16) ----
        float avk[8], avq[8];
        #pragma unroll
        for (int cc = 0; cc < 2; ++cc)
            #pragma unroll
            for (int rr = 0; rr < 2; ++rr)
                #pragma unroll
                for (int e = 0; e < 2; ++e) {
                    int c  = s * 16 + 2 * tig + e + 8 * cc;
                    int px = pxr + 8 * rr;
                    int i  = (rr + 2 * cc) * 2 + e;
                    avk[i] = __ldg(kvb + (size_t)c * HW + px);
                    avq[i] = __ldg(qb  + (size_t)c * HW + px);
                }

        u32 akh[4], akl[4], aqh[4], aql[4];
        #pragma unroll
        for (int i = 0; i < 4; ++i) {
            bsplit2(avk[2 * i], avk[2 * i + 1], akh[i], akl[i]);
            bsplit2(avq[2 * i], avq[2 * i + 1], aqh[i], aql[i]);
        }

        const ulonglong2* bp = &sBP[s * 384 + lane];
        #pragma unroll
        for (int j = 0; j < 8; ++j) {            // kv n-tiles
            ulonglong2 v = bp[j * 32];
            u32 bh0 = (u32)v.x, bh1 = (u32)(v.x >> 32);
            u32 bl0 = (u32)v.y, bl1 = (u32)(v.y >> 32);
            mma16816(acc[j], akh, bh0, bh1);
            mma16816(acc[j], akh, bl0, bl1);
            mma16816(acc[j], akl, bh0, bh1);
        }
        #pragma unroll
        for (int j = 8; j < 12; ++j) {           // q n-tiles
            ulonglong2 v = bp[j * 32];
            u32 bh0 = (u32)v.x, bh1 = (u32)(v.x >> 32);
            u32 bl0 = (u32)v.y, bl1 = (u32)(v.y >> 32);
            mma16816(acc[j], aqh, bh0, bh1);
            mma16816(acc[j], aqh, bl0, bl1);
            mma16816(acc[j], aql, bh0, bh1);
        }
    }

    // ---- gate in registers; x -> sX ----
    {
        const float scl = sScl;
        #pragma unroll
        for (int j = 0; j < 4; ++j) {
            float bk0, bk1, bv0, bv1, bq0, bq1;
            unpackf2(sBiasP[4 * j + tig],      bk0, bk1);
            unpackf2(sBiasP[16 + 4 * j + tig], bv0, bv1);
            unpackf2(sBiasP[32 + 4 * j + tig], bq0, bq1);
            #pragma unroll
            for (int rr = 0; rr < 2; ++rr) {
                float kk0 = acc[j][2 * rr]     + bk0;
                float kk1 = acc[j][2 * rr + 1] + bk1;
                float vv0 = acc[j + 4][2 * rr]     + bv0;
                float vv1 = acc[j + 4][2 * rr + 1] + bv1;
                float qq0 = acc[j + 8][2 * rr]     + bq0;
                float qq1 = acc[j + 8][2 * rr + 1] + bq1;
                float z0 = kk0 * qq0 * scl;
                float z1 = kk1 * qq1 * scl;
                float x0 = vv0 * __fdividef(1.0f, 1.0f + __expf(-z0));
                float x1 = vv1 * __fdividef(1.0f, 1.0f + __expf(-z1));
                int px = pxr + 8 * rr;
                *reinterpret_cast<float2*>(&sX[px * PITCHX + 8 * j + 2 * tig]) =
                    make_float2(x0, x1);
            }
        }
    }
    __syncthreads();

    // ---- chain: threads 0..127, one pixel each ----
    if (tid < TILE_PX) {
        const int px = tid;
        const float* row = sX + px * PITCHX;

        float x[32];
        #pragma unroll
        for (int o = 0; o < 32; o += 4) {
            float4 v4 = *reinterpret_cast<const float4*>(row + o);
            x[o] = v4.x; x[o+1] = v4.y; x[o+2] = v4.z; x[o+3] = v4.w;
        }

        u64 h1p[8];
        #pragma unroll
        for (int j = 0; j < 8; ++j) h1p[j] = 0ull;
        #pragma unroll
        for (int c = 0; c < 32; ++c) {
            u64 xx = packf2(x[c], x[c]);
            const ulonglong2* wr = reinterpret_cast<const ulonglong2*>(&sD1p[c * 8]);
            #pragma unroll
            for (int j = 0; j < 4; ++j) {
                ulonglong2 w = wr[j];
                h1p[2*j]   = ffma2(xx, w.x, h1p[2*j]);
                h1p[2*j+1] = ffma2(xx, w.y, h1p[2*j+1]);
            }
        }
        float h1[16];
        #pragma unroll
        for (int j = 0; j < 8; ++j) {
            float lo, hi; unpackf2(h1p[j], lo, hi);
            h1[2*j]   = fmaxf(lo, 0.0f);
            h1[2*j+1] = fmaxf(hi, 0.0f);
        }

        u64 h2p[4];
        #pragma unroll
        for (int j = 0; j < 4; ++j) h2p[j] = 0ull;
        #pragma unroll
        for (int c = 0; c < 16; ++c) {
            u64 xx = packf2(h1[c], h1[c]);
            const ulonglong2* wr = reinterpret_cast<const ulonglong2*>(&sD2p[c * 4]);
            #pragma unroll
            for (int j = 0; j < 2; ++j) {
                ulonglong2 w = wr[j];
                h2p[2*j]   = ffma2(xx, w.x, h2p[2*j]);
                h2p[2*j+1] = ffma2(xx, w.y, h2p[2*j+1]);
            }
        }
        float h2[8];
        #pragma unroll
        for (int j = 0; j < 4; ++j) {
            float lo, hi; unpackf2(h2p[j], lo, hi);
            h2[2*j]   = fmaxf(lo, 0.0f);
            h2[2*j+1] = fmaxf(hi, 0.0f);
        }

        u64 o16p[8];
        {
            const u64* b3p = reinterpret_cast<const u64*>(sB3);
            #pragma unroll
            for (int j = 0; j < 8; ++j) o16p[j] = b3p[j];
        }
        #pragma unroll
        for (int c = 0; c < 8; ++c) {
            u64 xx = packf2(h2[c], h2[c]);
            const ulonglong2* wr = reinterpret_cast<const ulonglong2*>(&sD3p[c * 8]);
            #pragma unroll
            for (int j = 0; j < 4; ++j) {
                ulonglong2 w = wr[j];
                o16p[2*j]   = ffma2(xx, w.x, o16p[2*j]);
                o16p[2*j+1] = ffma2(xx, w.y, o16p[2*j+1]);
            }
        }

        float* op = out + ((size_t)b * 16) * HW + poff + px;
        #pragma unroll
        for (int j = 0; j < 8; ++j) {
            float lo, hi; unpackf2(o16p[j], lo, hi);
            op[(size_t)(2*j) * HW]   = lo;
            op[(size_t)(2*j+1) * HW] = hi;
        }
    }
}

extern "C" void kernel_launch(void* const* d_in, const int* in_sizes, int n_in,
                              void* d_out, int out_size)
{
    fused_mma3_kernel<<<NBLK, TPB>>>(
        (const float*)d_in[0], (const float*)d_in[1],
        (const float*)d_in[2], (const float*)d_in[3],
        (const float*)d_in[4], (const float*)d_in[5],
        (const float*)d_in[6], (const float*)d_in[7],
        (const float*)d_in[8],
        (const float*)d_in[9], (const float*)d_in[10],
        (const float*)d_in[11], (const float*)d_in[12],
        (float*)d_out);
}